// round 13
// baseline (speedup 1.0000x reference)
#include <cuda_runtime.h>
#include <cuda_fp16.h>
#include <cuda_fp8.h>
#include <mma.h>
#include <math.h>

using namespace nvcuda;

// ---------------------------------------------------------------------------
// APPNP Link prediction.  N=50000, E=800000, P=200000, D=128, K=10 x 2, a=0.1
// Round 13: R12 base + manually software-pipelined SpMM body (next CSR entry
// and both gathers issued before consuming current pair -> 4-5 loads in
// flight per warp).  fp8 h + x0, 4B CSR, wmma GEMMs, PDL chain.
// ---------------------------------------------------------------------------

#define D 128
#define NMAX 50176
#define EMAX 800000
#define CSRMAX (EMAX + NMAX)
#define ALPHA 0.1f

struct __align__(4) CV4 { unsigned short c; __half v; };

__device__ unsigned g_a8 [NMAX * 32];    // fp8 ping
__device__ unsigned g_b8 [NMAX * 32];    // fp8 pong
__device__ unsigned g_x08[NMAX * 32];    // fp8 x0 (teleport term)
__device__ __half   g_h2[NMAX * D];      // final fp16 output (link head input)
__device__ __half   g_Wh1[D * D];
__device__ __half   g_Wh2[D * D];
__device__ int      g_deg[NMAX];
__device__ float    g_dinv[NMAX];
__device__ int      g_rowptr[NMAX + 1];
__device__ int      g_cursor[NMAX];
__device__ __align__(8) CV4 g_cv[CSRMAX];
__device__ int      g_bsums[64];

// ------------------------------------------------------------- fp8 helpers
__device__ __forceinline__ __half2 f8h2lo(unsigned r) {
    __half2_raw h = __nv_cvt_fp8x2_to_halfraw2((__nv_fp8x2_storage_t)(r & 0xffffu), __NV_E4M3);
    return *(__half2*)&h;
}
__device__ __forceinline__ __half2 f8h2hi(unsigned r) {
    __half2_raw h = __nv_cvt_fp8x2_to_halfraw2((__nv_fp8x2_storage_t)(r >> 16), __NV_E4M3);
    return *(__half2*)&h;
}
__device__ __forceinline__ float4 f8dec(unsigned r) {
    float2 a = __half22float2(f8h2lo(r));
    float2 b = __half22float2(f8h2hi(r));
    return make_float4(a.x, a.y, b.x, b.y);
}
__device__ __forceinline__ unsigned f8pack(float4 v) {
    __nv_fp8x2_storage_t lo = __nv_cvt_float2_to_fp8x2(make_float2(v.x, v.y), __NV_SATFINITE, __NV_E4M3);
    __nv_fp8x2_storage_t hi = __nv_cvt_float2_to_fp8x2(make_float2(v.z, v.w), __NV_SATFINITE, __NV_E4M3);
    return (unsigned)lo | ((unsigned)hi << 16);
}
__device__ __forceinline__ unsigned f8packh(__half2 a, __half2 b) {
    __half2_raw ra = *(__half2_raw*)&a;
    __half2_raw rb = *(__half2_raw*)&b;
    __nv_fp8x2_storage_t lo = __nv_cvt_halfraw2_to_fp8x2(ra, __NV_SATFINITE, __NV_E4M3);
    __nv_fp8x2_storage_t hi = __nv_cvt_halfraw2_to_fp8x2(rb, __NV_SATFINITE, __NV_E4M3);
    return (unsigned)lo | ((unsigned)hi << 16);
}

// ---------------------------------------------------------------- build
__global__ void k_prep(const float* __restrict__ W1, const float* __restrict__ W2,
                       int n) {
    int i = blockIdx.x * blockDim.x + threadIdx.x;
    if (i < n) { g_deg[i] = 1; g_cursor[i] = 0; }   // 1 = self loop
    if (i < D * D)      g_Wh1[i] = __float2half(W1[i]);
    else if (i < 2 * D * D) g_Wh2[i - D * D] = __float2half(W2[i - D * D]);
}

__global__ void k_hist(const int* __restrict__ dst, int e) {
    int i = blockIdx.x * blockDim.x + threadIdx.x;
    int d = (i < e) ? dst[i] : 0;          // prologue: input only
    cudaGridDependencySynchronize();       // wait for k_prep's g_deg init
    if (i < e) atomicAdd(&g_deg[d], 1);
}

__global__ void k_scanA(int n) {
    __shared__ int s[1024];
    int gid = blockIdx.x * 1024 + threadIdx.x;
    int v = (gid < n) ? g_deg[gid] : 0;
    s[threadIdx.x] = v;
    __syncthreads();
    for (int off = 1; off < 1024; off <<= 1) {
        int t = (threadIdx.x >= off) ? s[threadIdx.x - off] : 0;
        __syncthreads();
        s[threadIdx.x] += t;
        __syncthreads();
    }
    if (gid < n) g_rowptr[gid + 1] = s[threadIdx.x];
    if (threadIdx.x == 1023) g_bsums[blockIdx.x] = s[1023];
}

__global__ void k_scanC(int n) {
    __shared__ int sb[64];
    if (threadIdx.x < 64)
        sb[threadIdx.x] = (threadIdx.x < (int)gridDim.x) ? g_bsums[threadIdx.x] : 0;
    __syncthreads();
    int off = 0;
    for (int j = 0; j < (int)blockIdx.x; j++) off += sb[j];
    int gid = blockIdx.x * 1024 + threadIdx.x;
    if (gid < n) {
        g_rowptr[gid + 1] += off;
        g_dinv[gid] = rsqrtf((float)g_deg[gid]);
    }
    if (gid == 0) g_rowptr[0] = 0;
}

__global__ void k_fill(const int* __restrict__ src, const int* __restrict__ dst,
                       int e, int n) {
    int i = blockIdx.x * blockDim.x + threadIdx.x;
    int sv = 0, dv_ = 0;
    if (i < e) { sv = src[i]; dv_ = dst[i]; }      // prologue: inputs only
    cudaGridDependencySynchronize();               // wait for scanC (rowptr/dinv)
    if (i < e) {
        int pos = g_rowptr[dv_] + atomicAdd(&g_cursor[dv_], 1);
        CV4 cv; cv.c = (unsigned short)sv;
        cv.v = __float2half(0.9f * g_dinv[sv] * g_dinv[dv_]);
        g_cv[pos] = cv;
    } else if (i < e + n) {
        int nd = i - e;
        int pos = g_rowptr[nd] + atomicAdd(&g_cursor[nd], 1);
        float dv = g_dinv[nd];
        CV4 cv; cv.c = (unsigned short)nd;
        cv.v = __float2half(0.9f * dv * dv);
        g_cv[pos] = cv;
    }
}

// ---------------------------------------------------------------- GEMM (wmma)
__global__ void k_gemm(const float* __restrict__ Xext, const float* __restrict__ bias,
                       int mode, int nrows) {
    __shared__ __align__(32) char sbuf[16384];
    __half* Xs = (__half*)sbuf;          // [32][128] fp16
    float*  Cs = (float*)sbuf;           // [32][128] fp32 (reuse)

    int tid = threadIdx.x;
    int row0 = blockIdx.x * 32;
    const __half* Wh = mode ? g_Wh2 : g_Wh1;

    if (mode == 0) {
        for (int i = tid; i < 32 * 128; i += 256) {
            int r = i >> 7, k = i & 127;
            int row = row0 + r;
            float v = (row < nrows) ? Xext[row * 128 + k] : 0.f;
            Xs[i] = __float2half(v);
        }
        cudaGridDependencySynchronize();
    } else {
        cudaGridDependencySynchronize();
        for (int i = tid; i < 32 * 32; i += 256) {
            int r = i >> 5, j = i & 31;
            int row = row0 + r;
            float4 f = make_float4(0.f, 0.f, 0.f, 0.f);
            if (row < nrows) f = f8dec(g_a8[row * 32 + j]);
            int base = r * 128 + 4 * j;
            ((__half2*)Xs)[base / 2]     = __floats2half2_rn(fmaxf(f.x, 0.f), fmaxf(f.y, 0.f));
            ((__half2*)Xs)[base / 2 + 1] = __floats2half2_rn(fmaxf(f.z, 0.f), fmaxf(f.w, 0.f));
        }
    }
    __syncthreads();

    int w  = tid >> 5;
    int mi = w >> 2;
    int nj = w & 3;

    wmma::fragment<wmma::accumulator, 16, 16, 16, float> c0, c1;
    wmma::fill_fragment(c0, 0.f);
    wmma::fill_fragment(c1, 0.f);

#pragma unroll
    for (int k = 0; k < 128; k += 16) {
        wmma::fragment<wmma::matrix_a, 16, 16, 16, __half, wmma::row_major> a;
        wmma::load_matrix_sync(a, Xs + mi * 16 * 128 + k, 128);
        wmma::fragment<wmma::matrix_b, 16, 16, 16, __half, wmma::col_major> b0, b1;
        wmma::load_matrix_sync(b0, Wh + (nj * 32)      * 128 + k, 128);
        wmma::load_matrix_sync(b1, Wh + (nj * 32 + 16) * 128 + k, 128);
        wmma::mma_sync(c0, a, b0, c0);
        wmma::mma_sync(c1, a, b1, c1);
    }
    __syncthreads();
    wmma::store_matrix_sync(Cs + mi * 16 * 128 + nj * 32,      c0, 128, wmma::mem_row_major);
    wmma::store_matrix_sync(Cs + mi * 16 * 128 + nj * 32 + 16, c1, 128, wmma::mem_row_major);
    __syncthreads();

    for (int i = tid; i < 32 * 32; i += 256) {
        int r = i >> 5, j = i & 31;
        int row = row0 + r;
        if (row >= nrows) continue;
        int base = r * 128 + 4 * j;
        float4 v;
        v.x = Cs[base]     + bias[4 * j];
        v.y = Cs[base + 1] + bias[4 * j + 1];
        v.z = Cs[base + 2] + bias[4 * j + 2];
        v.w = Cs[base + 3] + bias[4 * j + 3];
        unsigned pk = f8pack(v);
        if (mode == 0) g_a8[row * 32 + j] = pk;
        else           g_b8[row * 32 + j] = pk;
        g_x08[row * 32 + j] = pk;
    }
}

// ---------------------------------------------------------------- APPNP fp8
// 2 rows per warp: half-warp (16 lanes) per row, lane = 8 fp8 features (uint2).
// Software-pipelined 2-wide body: next CSR entry + gathers issued before
// consuming the current pair (4-5 loads in flight per warp).
__global__ void __launch_bounds__(256) k_appnp8(int inIsA, int writeHalf, int n) {
    int gwarp = (blockIdx.x * blockDim.x + threadIdx.x) >> 5;
    int lane  = threadIdx.x & 31;
    int half  = lane >> 4;
    int l16   = lane & 15;
    int row   = gwarp * 2 + half;
    int s = 0, e = 0;
    uint2 xr = make_uint2(0u, 0u);
    if (row < n) {
        s = g_rowptr[row]; e = g_rowptr[row + 1];
        xr = ((const uint2*)g_x08)[row * 16 + l16];   // prologue prefetch
    }
    cudaGridDependencySynchronize();
    if (row >= n) return;

    const uint2* __restrict__ h = inIsA ? (const uint2*)g_a8 : (const uint2*)g_b8;

    __half2 z = __floats2half2_rn(0.f, 0.f);
    __half2 acc0 = z, acc1 = z, acc2 = z, acc3 = z;

    int i = s;
    if (i < e && (i & 1)) {                 // align to uint2
        CV4 cv = g_cv[i];
        uint2 r = h[(int)cv.c * 16 + l16];
        __half2 wv = __half2half2(cv.v);
        acc0 = __hfma2(wv, f8h2lo(r.x), acc0);
        acc1 = __hfma2(wv, f8h2hi(r.x), acc1);
        acc2 = __hfma2(wv, f8h2lo(r.y), acc2);
        acc3 = __hfma2(wv, f8h2hi(r.y), acc3);
        i++;
    }

    // -------- software-pipelined 2-wide body --------
    uint2 q  = make_uint2(0u, 0u);
    uint2 r0 = make_uint2(0u, 0u), r1 = make_uint2(0u, 0u);
    bool have = false;
    if (i + 1 < e) {                        // prime the pipeline
        q  = *(const uint2*)(g_cv + i);
        r0 = h[(int)(q.x & 0xffffu) * 16 + l16];
        r1 = h[(int)(q.y & 0xffffu) * 16 + l16];
        have = true;
        i += 2;
    }
    for (; i + 1 < e; i += 2) {
        // issue next loads FIRST (overlap their latency with consume below)
        uint2 qn = *(const uint2*)(g_cv + i);
        uint2 s0 = h[(int)(qn.x & 0xffffu) * 16 + l16];
        uint2 s1 = h[(int)(qn.y & 0xffffu) * 16 + l16];
        // consume current pair
        __half2 w0 = __half2half2(__ushort_as_half((unsigned short)(q.x >> 16)));
        __half2 w1 = __half2half2(__ushort_as_half((unsigned short)(q.y >> 16)));
        acc0 = __hfma2(w0, f8h2lo(r0.x), acc0);
        acc1 = __hfma2(w0, f8h2hi(r0.x), acc1);
        acc2 = __hfma2(w0, f8h2lo(r0.y), acc2);
        acc3 = __hfma2(w0, f8h2hi(r0.y), acc3);
        acc0 = __hfma2(w1, f8h2lo(r1.x), acc0);
        acc1 = __hfma2(w1, f8h2hi(r1.x), acc1);
        acc2 = __hfma2(w1, f8h2lo(r1.y), acc2);
        acc3 = __hfma2(w1, f8h2hi(r1.y), acc3);
        q = qn; r0 = s0; r1 = s1;
    }
    if (have) {                             // drain the pipeline
        __half2 w0 = __half2half2(__ushort_as_half((unsigned short)(q.x >> 16)));
        __half2 w1 = __half2half2(__ushort_as_half((unsigned short)(q.y >> 16)));
        acc0 = __hfma2(w0, f8h2lo(r0.x), acc0);
        acc1 = __hfma2(w0, f8h2hi(r0.x), acc1);
        acc2 = __hfma2(w0, f8h2lo(r0.y), acc2);
        acc3 = __hfma2(w0, f8h2hi(r0.y), acc3);
        acc0 = __hfma2(w1, f8h2lo(r1.x), acc0);
        acc1 = __hfma2(w1, f8h2hi(r1.x), acc1);
        acc2 = __hfma2(w1, f8h2lo(r1.y), acc2);
        acc3 = __hfma2(w1, f8h2hi(r1.y), acc3);
    }
    if (i < e) {                            // odd tail
        CV4 cv = g_cv[i];
        uint2 r = h[(int)cv.c * 16 + l16];
        __half2 wv = __half2half2(cv.v);
        acc0 = __hfma2(wv, f8h2lo(r.x), acc0);
        acc1 = __hfma2(wv, f8h2hi(r.x), acc1);
        acc2 = __hfma2(wv, f8h2lo(r.y), acc2);
        acc3 = __hfma2(wv, f8h2hi(r.y), acc3);
    }

    // teleport: + 0.1 * x0 (fp8, prefetched)
    __half2 al = __floats2half2_rn(ALPHA, ALPHA);
    acc0 = __hfma2(al, f8h2lo(xr.x), acc0);
    acc1 = __hfma2(al, f8h2hi(xr.x), acc1);
    acc2 = __hfma2(al, f8h2lo(xr.y), acc2);
    acc3 = __hfma2(al, f8h2hi(xr.y), acc3);

    if (writeHalf) {
        uint4 o;
        o.x = *(unsigned*)&acc0;
        o.y = *(unsigned*)&acc1;
        o.z = *(unsigned*)&acc2;
        o.w = *(unsigned*)&acc3;
        ((uint4*)g_h2)[row * 16 + l16] = o;
    } else {
        uint2* __restrict__ out = inIsA ? (uint2*)g_b8 : (uint2*)g_a8;
        uint2 o;
        o.x = f8packh(acc0, acc1);
        o.y = f8packh(acc2, acc3);
        out[row * 16 + l16] = o;
    }
}

// ---------------------------------------------------------------- link head
__global__ void k_link(const int* __restrict__ idx, const float* __restrict__ W3,
                       const float* __restrict__ b3, float* __restrict__ out, int p) {
    int w = (blockIdx.x * blockDim.x + threadIdx.x) >> 5;
    int lane = threadIdx.x & 31;
    int i0 = 0, i1 = 0;
    float w3a[4], w3b[4], w3c[4], w3d[4];
    float bb0 = 0.f, bb1 = 0.f;
    if (w < p) {
        i0 = idx[2 * w]; i1 = idx[2 * w + 1];
#pragma unroll
        for (int j = 0; j < 2; j++) {
            int k = 2 * (lane + 32 * j);
            w3a[2 * j]     = W3[k];       w3a[2 * j + 1] = W3[k + 1];
            w3b[2 * j]     = W3[128 + k]; w3b[2 * j + 1] = W3[128 + k + 1];
            w3c[2 * j]     = W3[256 + k]; w3c[2 * j + 1] = W3[256 + k + 1];
            w3d[2 * j]     = W3[384 + k]; w3d[2 * j + 1] = W3[384 + k + 1];
        }
        bb0 = b3[0]; bb1 = b3[1];
    }
    cudaGridDependencySynchronize();
    if (w >= p) return;

    const __half2* a2 = (const __half2*)(g_h2 + (size_t)i0 * 128);
    const __half2* b2 = (const __half2*)(g_h2 + (size_t)i1 * 128);
    float l0 = 0.f, l1 = 0.f;
#pragma unroll
    for (int j = 0; j < 2; j++) {
        int k2 = lane + 32 * j;
        float2 af = __half22float2(a2[k2]);
        float2 bf = __half22float2(b2[k2]);
        af.x = fmaxf(af.x, 0.f); af.y = fmaxf(af.y, 0.f);
        bf.x = fmaxf(bf.x, 0.f); bf.y = fmaxf(bf.y, 0.f);
        l0 += af.x * w3a[2 * j] + af.y * w3a[2 * j + 1]
            + bf.x * w3b[2 * j] + bf.y * w3b[2 * j + 1];
        l1 += af.x * w3c[2 * j] + af.y * w3c[2 * j + 1]
            + bf.x * w3d[2 * j] + bf.y * w3d[2 * j + 1];
    }
#pragma unroll
    for (int off = 16; off; off >>= 1) {
        l0 += __shfl_down_sync(0xffffffffu, l0, off);
        l1 += __shfl_down_sync(0xffffffffu, l1, off);
    }
    if (lane == 0) {
        l0 += bb0; l1 += bb1;
        float m = fmaxf(l0, l1);
        float lse = m + logf(expf(l0 - m) + expf(l1 - m));
        out[2 * w]     = l0 - lse;
        out[2 * w + 1] = l1 - lse;
    }
}

// ---------------------------------------------------------------- launch
template <typename... Args>
static void launch_pdl(void (*kern)(Args...), dim3 grid, dim3 block, int pdl,
                       Args... args) {
    cudaLaunchConfig_t cfg = {};
    cfg.gridDim = grid;
    cfg.blockDim = block;
    cfg.stream = 0;
    cudaLaunchAttribute attr[1];
    attr[0].id = cudaLaunchAttributeProgrammaticStreamSerialization;
    attr[0].val.programmaticStreamSerializationAllowed = 1;
    cfg.attrs = attr;
    cfg.numAttrs = pdl ? 1 : 0;
    cudaLaunchKernelEx(&cfg, kern, args...);
}

extern "C" void kernel_launch(void* const* d_in, const int* in_sizes, int n_in,
                              void* d_out, int out_size) {
    const float* x   = (const float*)d_in[0];
    const int*   ei  = (const int*)  d_in[1];
    const int*   idx = (const int*)  d_in[2];
    const float* W1  = (const float*)d_in[3];
    const float* b1  = (const float*)d_in[4];
    const float* W2  = (const float*)d_in[5];
    const float* b2  = (const float*)d_in[6];
    const float* W3  = (const float*)d_in[7];
    const float* b3  = (const float*)d_in[8];
    float* out = (float*)d_out;

    int N = in_sizes[0] / D;
    int E = in_sizes[1] / 2;
    int P = in_sizes[2] / 2;
    const int* src = ei;
    const int* dst = ei + E;

    int nbScan = (N + 1023) / 1024;

    // --- build ---
    k_prep<<<(N + 255) / 256, 256>>>(W1, W2, N);
    launch_pdl(k_hist, dim3((E + 255) / 256), dim3(256), 1, dst, E);
    k_scanA<<<nbScan, 1024>>>(N);
    k_scanC<<<nbScan, 1024>>>(N);
    launch_pdl(k_fill, dim3((E + N + 255) / 256), dim3(256), 1, src, dst, E, N);

    int gemmBlocks  = (N + 31) / 32;
    int appnpBlocks = ((N + 1) / 2 * 32 + 255) / 256;   // 2 rows per warp

    // --- phase 1 (fp8 propagation, ends in g_a8) ---
    launch_pdl(k_gemm, dim3(gemmBlocks), dim3(256), 1, x, b1, 0, N);
    for (int k = 0; k < 10; k++)
        launch_pdl(k_appnp8, dim3(appnpBlocks), dim3(256), k > 0, (k & 1) ^ 1, 0, N);

    // --- phase 2 (fp8 propagation, final step writes g_h2 fp16) ---
    launch_pdl(k_gemm, dim3(gemmBlocks), dim3(256), 1, (const float*)nullptr, b2, 1, N);
    for (int k = 0; k < 10; k++)
        launch_pdl(k_appnp8, dim3(appnpBlocks), dim3(256), k > 0, k & 1, (k == 9) ? 1 : 0, N);

    // --- link head ---
    launch_pdl(k_link, dim3((P * 32 + 255) / 256), dim3(256), 1, idx, W3, b3, out, P);
}

// round 14
// speedup vs baseline: 1.0282x; 1.0282x over previous
#include <cuda_runtime.h>
#include <cuda_fp16.h>
#include <cuda_fp8.h>
#include <mma.h>
#include <math.h>

using namespace nvcuda;

// ---------------------------------------------------------------------------
// APPNP Link prediction.  N=50000, E=800000, P=200000, D=128, K=10 x 2, a=0.1
// Round 14: R12 structure with 128-thread APPNP/link blocks (halve the
// partial-wave tail).  fp8 h + x0, 4B CSR, wmma GEMMs, PDL chain.
// ---------------------------------------------------------------------------

#define D 128
#define NMAX 50176
#define EMAX 800000
#define CSRMAX (EMAX + NMAX)
#define ALPHA 0.1f

struct __align__(4) CV4 { unsigned short c; __half v; };

__device__ unsigned g_a8 [NMAX * 32];    // fp8 ping
__device__ unsigned g_b8 [NMAX * 32];    // fp8 pong
__device__ unsigned g_x08[NMAX * 32];    // fp8 x0 (teleport term)
__device__ __half   g_h2[NMAX * D];      // final fp16 output (link head input)
__device__ __half   g_Wh1[D * D];
__device__ __half   g_Wh2[D * D];
__device__ int      g_deg[NMAX];
__device__ float    g_dinv[NMAX];
__device__ int      g_rowptr[NMAX + 1];
__device__ int      g_cursor[NMAX];
__device__ __align__(8) CV4 g_cv[CSRMAX];
__device__ int      g_bsums[64];

// ------------------------------------------------------------- fp8 helpers
__device__ __forceinline__ __half2 f8h2lo(unsigned r) {
    __half2_raw h = __nv_cvt_fp8x2_to_halfraw2((__nv_fp8x2_storage_t)(r & 0xffffu), __NV_E4M3);
    return *(__half2*)&h;
}
__device__ __forceinline__ __half2 f8h2hi(unsigned r) {
    __half2_raw h = __nv_cvt_fp8x2_to_halfraw2((__nv_fp8x2_storage_t)(r >> 16), __NV_E4M3);
    return *(__half2*)&h;
}
__device__ __forceinline__ float4 f8dec(unsigned r) {
    float2 a = __half22float2(f8h2lo(r));
    float2 b = __half22float2(f8h2hi(r));
    return make_float4(a.x, a.y, b.x, b.y);
}
__device__ __forceinline__ unsigned f8pack(float4 v) {
    __nv_fp8x2_storage_t lo = __nv_cvt_float2_to_fp8x2(make_float2(v.x, v.y), __NV_SATFINITE, __NV_E4M3);
    __nv_fp8x2_storage_t hi = __nv_cvt_float2_to_fp8x2(make_float2(v.z, v.w), __NV_SATFINITE, __NV_E4M3);
    return (unsigned)lo | ((unsigned)hi << 16);
}
__device__ __forceinline__ unsigned f8packh(__half2 a, __half2 b) {
    __half2_raw ra = *(__half2_raw*)&a;
    __half2_raw rb = *(__half2_raw*)&b;
    __nv_fp8x2_storage_t lo = __nv_cvt_halfraw2_to_fp8x2(ra, __NV_SATFINITE, __NV_E4M3);
    __nv_fp8x2_storage_t hi = __nv_cvt_halfraw2_to_fp8x2(rb, __NV_SATFINITE, __NV_E4M3);
    return (unsigned)lo | ((unsigned)hi << 16);
}

// ---------------------------------------------------------------- build
__global__ void k_prep(const float* __restrict__ W1, const float* __restrict__ W2,
                       int n) {
    int i = blockIdx.x * blockDim.x + threadIdx.x;
    if (i < n) { g_deg[i] = 1; g_cursor[i] = 0; }   // 1 = self loop
    if (i < D * D)      g_Wh1[i] = __float2half(W1[i]);
    else if (i < 2 * D * D) g_Wh2[i - D * D] = __float2half(W2[i - D * D]);
}

__global__ void k_hist(const int* __restrict__ dst, int e) {
    int i = blockIdx.x * blockDim.x + threadIdx.x;
    int d = (i < e) ? dst[i] : 0;          // prologue: input only
    cudaGridDependencySynchronize();       // wait for k_prep's g_deg init
    if (i < e) atomicAdd(&g_deg[d], 1);
}

__global__ void k_scanA(int n) {
    __shared__ int s[1024];
    int gid = blockIdx.x * 1024 + threadIdx.x;
    int v = (gid < n) ? g_deg[gid] : 0;
    s[threadIdx.x] = v;
    __syncthreads();
    for (int off = 1; off < 1024; off <<= 1) {
        int t = (threadIdx.x >= off) ? s[threadIdx.x - off] : 0;
        __syncthreads();
        s[threadIdx.x] += t;
        __syncthreads();
    }
    if (gid < n) g_rowptr[gid + 1] = s[threadIdx.x];
    if (threadIdx.x == 1023) g_bsums[blockIdx.x] = s[1023];
}

__global__ void k_scanC(int n) {
    __shared__ int sb[64];
    if (threadIdx.x < 64)
        sb[threadIdx.x] = (threadIdx.x < (int)gridDim.x) ? g_bsums[threadIdx.x] : 0;
    __syncthreads();
    int off = 0;
    for (int j = 0; j < (int)blockIdx.x; j++) off += sb[j];
    int gid = blockIdx.x * 1024 + threadIdx.x;
    if (gid < n) {
        g_rowptr[gid + 1] += off;
        g_dinv[gid] = rsqrtf((float)g_deg[gid]);
    }
    if (gid == 0) g_rowptr[0] = 0;
}

__global__ void k_fill(const int* __restrict__ src, const int* __restrict__ dst,
                       int e, int n) {
    int i = blockIdx.x * blockDim.x + threadIdx.x;
    int sv = 0, dv_ = 0;
    if (i < e) { sv = src[i]; dv_ = dst[i]; }      // prologue: inputs only
    cudaGridDependencySynchronize();               // wait for scanC (rowptr/dinv)
    if (i < e) {
        int pos = g_rowptr[dv_] + atomicAdd(&g_cursor[dv_], 1);
        CV4 cv; cv.c = (unsigned short)sv;
        cv.v = __float2half(0.9f * g_dinv[sv] * g_dinv[dv_]);
        g_cv[pos] = cv;
    } else if (i < e + n) {
        int nd = i - e;
        int pos = g_rowptr[nd] + atomicAdd(&g_cursor[nd], 1);
        float dv = g_dinv[nd];
        CV4 cv; cv.c = (unsigned short)nd;
        cv.v = __float2half(0.9f * dv * dv);
        g_cv[pos] = cv;
    }
}

// ---------------------------------------------------------------- GEMM (wmma)
__global__ void k_gemm(const float* __restrict__ Xext, const float* __restrict__ bias,
                       int mode, int nrows) {
    __shared__ __align__(32) char sbuf[16384];
    __half* Xs = (__half*)sbuf;          // [32][128] fp16
    float*  Cs = (float*)sbuf;           // [32][128] fp32 (reuse)

    int tid = threadIdx.x;
    int row0 = blockIdx.x * 32;
    const __half* Wh = mode ? g_Wh2 : g_Wh1;

    if (mode == 0) {
        for (int i = tid; i < 32 * 128; i += 256) {
            int r = i >> 7, k = i & 127;
            int row = row0 + r;
            float v = (row < nrows) ? Xext[row * 128 + k] : 0.f;
            Xs[i] = __float2half(v);
        }
        cudaGridDependencySynchronize();
    } else {
        cudaGridDependencySynchronize();
        for (int i = tid; i < 32 * 32; i += 256) {
            int r = i >> 5, j = i & 31;
            int row = row0 + r;
            float4 f = make_float4(0.f, 0.f, 0.f, 0.f);
            if (row < nrows) f = f8dec(g_a8[row * 32 + j]);
            int base = r * 128 + 4 * j;
            ((__half2*)Xs)[base / 2]     = __floats2half2_rn(fmaxf(f.x, 0.f), fmaxf(f.y, 0.f));
            ((__half2*)Xs)[base / 2 + 1] = __floats2half2_rn(fmaxf(f.z, 0.f), fmaxf(f.w, 0.f));
        }
    }
    __syncthreads();

    int w  = tid >> 5;
    int mi = w >> 2;
    int nj = w & 3;

    wmma::fragment<wmma::accumulator, 16, 16, 16, float> c0, c1;
    wmma::fill_fragment(c0, 0.f);
    wmma::fill_fragment(c1, 0.f);

#pragma unroll
    for (int k = 0; k < 128; k += 16) {
        wmma::fragment<wmma::matrix_a, 16, 16, 16, __half, wmma::row_major> a;
        wmma::load_matrix_sync(a, Xs + mi * 16 * 128 + k, 128);
        wmma::fragment<wmma::matrix_b, 16, 16, 16, __half, wmma::col_major> b0, b1;
        wmma::load_matrix_sync(b0, Wh + (nj * 32)      * 128 + k, 128);
        wmma::load_matrix_sync(b1, Wh + (nj * 32 + 16) * 128 + k, 128);
        wmma::mma_sync(c0, a, b0, c0);
        wmma::mma_sync(c1, a, b1, c1);
    }
    __syncthreads();
    wmma::store_matrix_sync(Cs + mi * 16 * 128 + nj * 32,      c0, 128, wmma::mem_row_major);
    wmma::store_matrix_sync(Cs + mi * 16 * 128 + nj * 32 + 16, c1, 128, wmma::mem_row_major);
    __syncthreads();

    for (int i = tid; i < 32 * 32; i += 256) {
        int r = i >> 5, j = i & 31;
        int row = row0 + r;
        if (row >= nrows) continue;
        int base = r * 128 + 4 * j;
        float4 v;
        v.x = Cs[base]     + bias[4 * j];
        v.y = Cs[base + 1] + bias[4 * j + 1];
        v.z = Cs[base + 2] + bias[4 * j + 2];
        v.w = Cs[base + 3] + bias[4 * j + 3];
        unsigned pk = f8pack(v);
        if (mode == 0) g_a8[row * 32 + j] = pk;
        else           g_b8[row * 32 + j] = pk;
        g_x08[row * 32 + j] = pk;
    }
}

// ---------------------------------------------------------------- APPNP fp8
// 2 rows per warp: half-warp (16 lanes) per row, lane = 8 fp8 features (uint2).
// 128-thread blocks (8 rows) to halve the partial-wave tail.
__global__ void __launch_bounds__(128) k_appnp8(int inIsA, int writeHalf, int n) {
    int gwarp = (blockIdx.x * blockDim.x + threadIdx.x) >> 5;
    int lane  = threadIdx.x & 31;
    int half  = lane >> 4;
    int l16   = lane & 15;
    int row   = gwarp * 2 + half;
    int s = 0, e = 0;
    uint2 xr = make_uint2(0u, 0u);
    if (row < n) {
        s = g_rowptr[row]; e = g_rowptr[row + 1];
        xr = ((const uint2*)g_x08)[row * 16 + l16];   // prologue prefetch
    }
    cudaGridDependencySynchronize();
    if (row >= n) return;

    const uint2* __restrict__ h = inIsA ? (const uint2*)g_a8 : (const uint2*)g_b8;

    __half2 z = __floats2half2_rn(0.f, 0.f);
    __half2 acc0 = z, acc1 = z, acc2 = z, acc3 = z;

    int i = s;
    if (i < e && (i & 1)) {                 // align to uint2
        CV4 cv = g_cv[i];
        uint2 r = h[(int)cv.c * 16 + l16];
        __half2 wv = __half2half2(cv.v);
        acc0 = __hfma2(wv, f8h2lo(r.x), acc0);
        acc1 = __hfma2(wv, f8h2hi(r.x), acc1);
        acc2 = __hfma2(wv, f8h2lo(r.y), acc2);
        acc3 = __hfma2(wv, f8h2hi(r.y), acc3);
        i++;
    }
    for (; i + 1 < e; i += 2) {             // 2 CSR entries per 8B load
        uint2 q = *(const uint2*)(g_cv + i);
        uint2 r0 = h[(int)(q.x & 0xffffu) * 16 + l16];
        uint2 r1 = h[(int)(q.y & 0xffffu) * 16 + l16];
        __half2 w0 = __half2half2(__ushort_as_half((unsigned short)(q.x >> 16)));
        __half2 w1 = __half2half2(__ushort_as_half((unsigned short)(q.y >> 16)));
        acc0 = __hfma2(w0, f8h2lo(r0.x), acc0);
        acc1 = __hfma2(w0, f8h2hi(r0.x), acc1);
        acc2 = __hfma2(w0, f8h2lo(r0.y), acc2);
        acc3 = __hfma2(w0, f8h2hi(r0.y), acc3);
        acc0 = __hfma2(w1, f8h2lo(r1.x), acc0);
        acc1 = __hfma2(w1, f8h2hi(r1.x), acc1);
        acc2 = __hfma2(w1, f8h2lo(r1.y), acc2);
        acc3 = __hfma2(w1, f8h2hi(r1.y), acc3);
    }
    if (i < e) {                            // tail
        CV4 cv = g_cv[i];
        uint2 r = h[(int)cv.c * 16 + l16];
        __half2 wv = __half2half2(cv.v);
        acc0 = __hfma2(wv, f8h2lo(r.x), acc0);
        acc1 = __hfma2(wv, f8h2hi(r.x), acc1);
        acc2 = __hfma2(wv, f8h2lo(r.y), acc2);
        acc3 = __hfma2(wv, f8h2hi(r.y), acc3);
    }

    // teleport: + 0.1 * x0 (fp8, prefetched)
    __half2 al = __floats2half2_rn(ALPHA, ALPHA);
    acc0 = __hfma2(al, f8h2lo(xr.x), acc0);
    acc1 = __hfma2(al, f8h2hi(xr.x), acc1);
    acc2 = __hfma2(al, f8h2lo(xr.y), acc2);
    acc3 = __hfma2(al, f8h2hi(xr.y), acc3);

    if (writeHalf) {
        uint4 o;
        o.x = *(unsigned*)&acc0;
        o.y = *(unsigned*)&acc1;
        o.z = *(unsigned*)&acc2;
        o.w = *(unsigned*)&acc3;
        ((uint4*)g_h2)[row * 16 + l16] = o;
    } else {
        uint2* __restrict__ out = inIsA ? (uint2*)g_b8 : (uint2*)g_a8;
        uint2 o;
        o.x = f8packh(acc0, acc1);
        o.y = f8packh(acc2, acc3);
        out[row * 16 + l16] = o;
    }
}

// ---------------------------------------------------------------- link head
__global__ void __launch_bounds__(128) k_link(
        const int* __restrict__ idx, const float* __restrict__ W3,
        const float* __restrict__ b3, float* __restrict__ out, int p) {
    int w = (blockIdx.x * blockDim.x + threadIdx.x) >> 5;
    int lane = threadIdx.x & 31;
    int i0 = 0, i1 = 0;
    float w3a[4], w3b[4], w3c[4], w3d[4];
    float bb0 = 0.f, bb1 = 0.f;
    if (w < p) {
        i0 = idx[2 * w]; i1 = idx[2 * w + 1];
#pragma unroll
        for (int j = 0; j < 2; j++) {
            int k = 2 * (lane + 32 * j);
            w3a[2 * j]     = W3[k];       w3a[2 * j + 1] = W3[k + 1];
            w3b[2 * j]     = W3[128 + k]; w3b[2 * j + 1] = W3[128 + k + 1];
            w3c[2 * j]     = W3[256 + k]; w3c[2 * j + 1] = W3[256 + k + 1];
            w3d[2 * j]     = W3[384 + k]; w3d[2 * j + 1] = W3[384 + k + 1];
        }
        bb0 = b3[0]; bb1 = b3[1];
    }
    cudaGridDependencySynchronize();
    if (w >= p) return;

    const __half2* a2 = (const __half2*)(g_h2 + (size_t)i0 * 128);
    const __half2* b2 = (const __half2*)(g_h2 + (size_t)i1 * 128);
    float l0 = 0.f, l1 = 0.f;
#pragma unroll
    for (int j = 0; j < 2; j++) {
        int k2 = lane + 32 * j;
        float2 af = __half22float2(a2[k2]);
        float2 bf = __half22float2(b2[k2]);
        af.x = fmaxf(af.x, 0.f); af.y = fmaxf(af.y, 0.f);
        bf.x = fmaxf(bf.x, 0.f); bf.y = fmaxf(bf.y, 0.f);
        l0 += af.x * w3a[2 * j] + af.y * w3a[2 * j + 1]
            + bf.x * w3b[2 * j] + bf.y * w3b[2 * j + 1];
        l1 += af.x * w3c[2 * j] + af.y * w3c[2 * j + 1]
            + bf.x * w3d[2 * j] + bf.y * w3d[2 * j + 1];
    }
#pragma unroll
    for (int off = 16; off; off >>= 1) {
        l0 += __shfl_down_sync(0xffffffffu, l0, off);
        l1 += __shfl_down_sync(0xffffffffu, l1, off);
    }
    if (lane == 0) {
        l0 += bb0; l1 += bb1;
        float m = fmaxf(l0, l1);
        float lse = m + logf(expf(l0 - m) + expf(l1 - m));
        out[2 * w]     = l0 - lse;
        out[2 * w + 1] = l1 - lse;
    }
}

// ---------------------------------------------------------------- launch
template <typename... Args>
static void launch_pdl(void (*kern)(Args...), dim3 grid, dim3 block, int pdl,
                       Args... args) {
    cudaLaunchConfig_t cfg = {};
    cfg.gridDim = grid;
    cfg.blockDim = block;
    cfg.stream = 0;
    cudaLaunchAttribute attr[1];
    attr[0].id = cudaLaunchAttributeProgrammaticStreamSerialization;
    attr[0].val.programmaticStreamSerializationAllowed = 1;
    cfg.attrs = attr;
    cfg.numAttrs = pdl ? 1 : 0;
    cudaLaunchKernelEx(&cfg, kern, args...);
}

extern "C" void kernel_launch(void* const* d_in, const int* in_sizes, int n_in,
                              void* d_out, int out_size) {
    const float* x   = (const float*)d_in[0];
    const int*   ei  = (const int*)  d_in[1];
    const int*   idx = (const int*)  d_in[2];
    const float* W1  = (const float*)d_in[3];
    const float* b1  = (const float*)d_in[4];
    const float* W2  = (const float*)d_in[5];
    const float* b2  = (const float*)d_in[6];
    const float* W3  = (const float*)d_in[7];
    const float* b3  = (const float*)d_in[8];
    float* out = (float*)d_out;

    int N = in_sizes[0] / D;
    int E = in_sizes[1] / 2;
    int P = in_sizes[2] / 2;
    const int* src = ei;
    const int* dst = ei + E;

    int nbScan = (N + 1023) / 1024;

    // --- build ---
    k_prep<<<(N + 255) / 256, 256>>>(W1, W2, N);
    launch_pdl(k_hist, dim3((E + 255) / 256), dim3(256), 1, dst, E);
    k_scanA<<<nbScan, 1024>>>(N);
    k_scanC<<<nbScan, 1024>>>(N);
    launch_pdl(k_fill, dim3((E + N + 255) / 256), dim3(256), 1, src, dst, E, N);

    int gemmBlocks  = (N + 31) / 32;
    int appnpBlocks = ((N + 1) / 2 * 32 + 127) / 128;   // 2 rows/warp, 128-thr blocks

    // --- phase 1 (fp8 propagation, ends in g_a8) ---
    launch_pdl(k_gemm, dim3(gemmBlocks), dim3(256), 1, x, b1, 0, N);
    for (int k = 0; k < 10; k++)
        launch_pdl(k_appnp8, dim3(appnpBlocks), dim3(128), k > 0, (k & 1) ^ 1, 0, N);

    // --- phase 2 (fp8 propagation, final step writes g_h2 fp16) ---
    launch_pdl(k_gemm, dim3(gemmBlocks), dim3(256), 1, (const float*)nullptr, b2, 1, N);
    for (int k = 0; k < 10; k++)
        launch_pdl(k_appnp8, dim3(appnpBlocks), dim3(128), k > 0, k & 1, (k == 9) ? 1 : 0, N);

    // --- link head ---
    launch_pdl(k_link, dim3((P * 32 + 127) / 128), dim3(128), 1, idx, W3, b3, out, P);
}